// round 7
// baseline (speedup 1.0000x reference)
#include <cuda_runtime.h>

#define HNUM 16
#define NSEQ 2048
#define DDIM 64
#define CHK  64
#define NC   (NSEQ / CHK)      // 32 chunks
#define NB   (HNUM * NC)       // 512 (head, chunk) tiles
#define EPSV 1e-6f

#define ST 68                  // padded stride for transposed tiles / A

// Scratch
__device__ float g_KV[(size_t)NB * DDIM * DDIM];   // per-chunk KV sums -> exclusive prefix (8 MB)
__device__ float g_Kz[(size_t)NB * DDIM];          // per-chunk K colsum -> exclusive prefix
__device__ float g_P[(size_t)NB * CHK * DDIM];     // intra-chunk partial A@V (8 MB)
__device__ float g_denp[(size_t)NB * CHK];         // partial denominator (EPS + rowsum A)

__device__ __forceinline__ float fmap(float x) {
    // elu(x) + 1 : x>0 -> x+1 ; x<=0 -> exp(x)
    return x > 0.f ? x + 1.f : __expf(x);
}

// ---------------------------------------------------------------------------
// Fused kernel: grid = 2*NB (1024), block = 256.
//   even blockIdx -> phase1 body (KV = phiK^T V, Kz = colsum)   [R2 verbatim]
//   odd  blockIdx -> intra-chunk body: A = phiQ phiK^T (masked),
//                    denp = EPS + rowsum(A), P = A @ V (causal-truncated)
// Interleaving mixes LDS-heavy and FMA-heavy CTAs on each SM.
// ---------------------------------------------------------------------------
__global__ void __launch_bounds__(256) lin_fused(const float* __restrict__ Qg,
                                                 const float* __restrict__ Kg,
                                                 const float* __restrict__ Vg) {
    extern __shared__ float sm[];
    const int tid  = threadIdx.x;
    const int tile = blockIdx.x >> 1;
    const size_t base = (size_t)tile * (CHK * DDIM);

    if ((blockIdx.x & 1) == 0) {
        // ================= phase1 body (verbatim R2) =================
        float* sK = sm;                    // CHK*DDIM
        float* sV = sm + CHK * DDIM;       // CHK*DDIM

        #pragma unroll
        for (int s = 0; s < 4; s++) {
            int i4 = tid + s * 256;
            float4 k = ((const float4*)(Kg + base))[i4];
            float4 v = ((const float4*)(Vg + base))[i4];
            k.x = fmap(k.x); k.y = fmap(k.y); k.z = fmap(k.z); k.w = fmap(k.w);
            ((float4*)sK)[i4] = k;
            ((float4*)sV)[i4] = v;
        }
        __syncthreads();

        const int d0 = (tid >> 4) * 4;
        const int e0 = (tid & 15) * 4;
        float acc[4][4] = {};
        #pragma unroll 8
        for (int m = 0; m < CHK; m++) {
            float4 kf = *(const float4*)&sK[m * DDIM + d0];
            float4 vf = *(const float4*)&sV[m * DDIM + e0];
            float kk[4] = {kf.x, kf.y, kf.z, kf.w};
            float vv[4] = {vf.x, vf.y, vf.z, vf.w};
            #pragma unroll
            for (int a = 0; a < 4; a++)
                #pragma unroll
                for (int b = 0; b < 4; b++)
                    acc[a][b] += kk[a] * vv[b];
        }

        float* kvo = g_KV + (size_t)tile * (DDIM * DDIM);
        #pragma unroll
        for (int a = 0; a < 4; a++)
            *(float4*)&kvo[(d0 + a) * DDIM + e0] =
                make_float4(acc[a][0], acc[a][1], acc[a][2], acc[a][3]);

        if (tid < DDIM) {
            float s = 0.f;
            #pragma unroll 8
            for (int m = 0; m < CHK; m++) s += sK[m * DDIM + tid];
            g_Kz[(size_t)tile * DDIM + tid] = s;
        }
    } else {
        // ========== intra-chunk body: A, denp, P = A@V ==========
        float* sQt  = sm;                   // [d][m] DDIM*ST
        float* sKt  = sQt + DDIM * ST;      // [d][j] DDIM*ST
        float* sV   = sKt + DDIM * ST;      // [k][e] CHK*DDIM
        float* sAt  = sV  + CHK * DDIM;     // [k][m] CHK*ST

        // load + feature map + transpose Q,K; V row-major
        {
            const int m  = tid >> 2;
            const int d0 = (tid & 3) * 16;
            #pragma unroll
            for (int u = 0; u < 4; u++) {
                int col = d0 + 4 * u;
                float4 q = *(const float4*)(Qg + base + m * DDIM + col);
                float4 k = *(const float4*)(Kg + base + m * DDIM + col);
                float4 v = *(const float4*)(Vg + base + m * DDIM + col);
                sQt[(col + 0) * ST + m] = fmap(q.x);
                sQt[(col + 1) * ST + m] = fmap(q.y);
                sQt[(col + 2) * ST + m] = fmap(q.z);
                sQt[(col + 3) * ST + m] = fmap(q.w);
                sKt[(col + 0) * ST + m] = fmap(k.x);
                sKt[(col + 1) * ST + m] = fmap(k.y);
                sKt[(col + 2) * ST + m] = fmap(k.z);
                sKt[(col + 3) * ST + m] = fmap(k.w);
                *(float4*)&sV[m * DDIM + col] = v;
            }
        }
        __syncthreads();

        // A-phase (verbatim)
        {
            const int rbase = (tid >> 4) * 4;
            const int cbase = (tid & 15) * 4;
            float acc[4][4] = {};
            #pragma unroll 8
            for (int d = 0; d < DDIM; d++) {
                float4 qf = *(const float4*)&sQt[d * ST + rbase];
                float4 kf = *(const float4*)&sKt[d * ST + cbase];
                float qq[4] = {qf.x, qf.y, qf.z, qf.w};
                float kk[4] = {kf.x, kf.y, kf.z, kf.w};
                #pragma unroll
                for (int a = 0; a < 4; a++)
                    #pragma unroll
                    for (int b = 0; b < 4; b++)
                        acc[a][b] += qq[a] * kk[b];
            }
            #pragma unroll
            for (int b = 0; b < 4; b++) {
                int col = cbase + b;
                float4 o;
                o.x = (col <= rbase + 0) ? acc[0][b] : 0.f;
                o.y = (col <= rbase + 1) ? acc[1][b] : 0.f;
                o.z = (col <= rbase + 2) ? acc[2][b] : 0.f;
                o.w = (col <= rbase + 3) ? acc[3][b] : 0.f;
                *(float4*)&sAt[col * ST + rbase] = o;
            }
        }
        __syncthreads();

        // partial denominator: EPS + rowsum(A_masked)
        if (tid < CHK) {
            float s = EPSV;
            #pragma unroll 8
            for (int k = 0; k < CHK; k++) s += sAt[k * ST + tid];
            g_denp[(size_t)tile * CHK + tid] = s;
        }

        // P = A@V, balanced causal row-pairing (R6 measured-correct body)
        {
            const int w    = tid >> 5;
            const int half = (tid >> 4) & 1;
            const int cb   = (tid & 15) * 4;
            const int rL   = 4 * w + 2 * half;
            const int rH   = 60 - 4 * w + 2 * half;

            float accL[2][4] = {};
            float accH[2][4] = {};

            #pragma unroll
            for (int s = 0; s < 16; s++) {
                if (s < w + 1) {
                    #pragma unroll
                    for (int kk = 0; kk < 4; kk++) {
                        int k = s * 4 + kk;
                        float2 aL = *(const float2*)&sAt[k * ST + rL];
                        float2 aH = *(const float2*)&sAt[k * ST + rH];
                        float4 vf = *(const float4*)&sV[k * DDIM + cb];
                        float vv[4] = {vf.x, vf.y, vf.z, vf.w};
                        #pragma unroll
                        for (int b = 0; b < 4; b++) {
                            accL[0][b] += aL.x * vv[b];
                            accL[1][b] += aL.y * vv[b];
                            accH[0][b] += aH.x * vv[b];
                            accH[1][b] += aH.y * vv[b];
                        }
                    }
                } else if (s < 16 - w) {
                    #pragma unroll
                    for (int kk = 0; kk < 4; kk++) {
                        int k = s * 4 + kk;
                        float2 aH = *(const float2*)&sAt[k * ST + rH];
                        float4 vf = *(const float4*)&sV[k * DDIM + cb];
                        float vv[4] = {vf.x, vf.y, vf.z, vf.w};
                        #pragma unroll
                        for (int b = 0; b < 4; b++) {
                            accH[0][b] += aH.x * vv[b];
                            accH[1][b] += aH.y * vv[b];
                        }
                    }
                }
            }

            float* Pg = g_P + base;
            #pragma unroll
            for (int i = 0; i < 2; i++) {
                *(float4*)&Pg[(size_t)(rL + i) * DDIM + cb] =
                    make_float4(accL[i][0], accL[i][1], accL[i][2], accL[i][3]);
                *(float4*)&Pg[(size_t)(rH + i) * DDIM + cb] =
                    make_float4(accH[i][0], accH[i][1], accH[i][2], accH[i][3]);
            }
        }
    }
}

// ---------------------------------------------------------------------------
// Phase 2: in-place exclusive prefix over 32 chunks (per head). [R2 verbatim]
// grid = 16 heads * 8 parts = 128, block = 512
// ---------------------------------------------------------------------------
__global__ void __launch_bounds__(512) lin_phase2() {
    const int h = blockIdx.x >> 3;
    const int part = blockIdx.x & 7;
    const int idx = part * 512 + threadIdx.x;   // 0..4095

    float run = 0.f;
    #pragma unroll
    for (int c = 0; c < NC; c++) {
        float* p = g_KV + ((size_t)(h * NC + c)) * (DDIM * DDIM) + idx;
        float v = *p;
        *p = run;
        run += v;
    }
    if (part == 0 && threadIdx.x < DDIM) {
        float rz = 0.f;
        #pragma unroll
        for (int c = 0; c < NC; c++) {
            float* p = g_Kz + (size_t)(h * NC + c) * DDIM + threadIdx.x;
            float v = *p;
            *p = rz;
            rz += v;
        }
    }
}

// ---------------------------------------------------------------------------
// Epilogue: out = (P + phiQ @ S_excl) / (denp + phiQ . z_excl)
// grid = NB (512), block = 256, ~33.5 KB smem (high occupancy)
// ---------------------------------------------------------------------------
__global__ void __launch_bounds__(256) lin_epi(const float* __restrict__ Qg,
                                               float* __restrict__ Og) {
    extern __shared__ float sm[];
    float* sQt  = sm;                   // [d][m] DDIM*ST
    float* sS   = sQt + DDIM * ST;      // [d][e] DDIM*DDIM
    float* sZ   = sS  + DDIM * DDIM;    // DDIM
    float* sDen = sZ  + DDIM;           // CHK

    const int tid = threadIdx.x;
    const int tile = blockIdx.x;
    const size_t base = (size_t)tile * (CHK * DDIM);

    // load Q (fmap, transposed), S (exclusive prefix), z
    {
        const int m  = tid >> 2;
        const int d0 = (tid & 3) * 16;
        #pragma unroll
        for (int u = 0; u < 4; u++) {
            int col = d0 + 4 * u;
            float4 q = *(const float4*)(Qg + base + m * DDIM + col);
            sQt[(col + 0) * ST + m] = fmap(q.x);
            sQt[(col + 1) * ST + m] = fmap(q.y);
            sQt[(col + 2) * ST + m] = fmap(q.z);
            sQt[(col + 3) * ST + m] = fmap(q.w);
        }
        const float4* Sg4 = (const float4*)(g_KV + (size_t)tile * (DDIM * DDIM));
        #pragma unroll
        for (int s = 0; s < 4; s++)
            ((float4*)sS)[tid + s * 256] = Sg4[tid + s * 256];
        if (tid < DDIM) sZ[tid] = g_Kz[(size_t)tile * DDIM + tid];
    }
    __syncthreads();

    // complete the denominator
    if (tid < CHK) {
        float s = g_denp[(size_t)tile * CHK + tid];
        #pragma unroll 8
        for (int d = 0; d < DDIM; d++) s += sQt[d * ST + tid] * sZ[d];
        sDen[tid] = 1.f / s;
    }
    __syncthreads();

    // Q@S (4x4 tiles), add P, scale, write out
    {
        const int rbase = (tid >> 4) * 4;
        const int cbase = (tid & 15) * 4;
        float acc[4][4] = {};
        #pragma unroll 8
        for (int d = 0; d < DDIM; d++) {
            float4 qf = *(const float4*)&sQt[d * ST + rbase];
            float4 sf = *(const float4*)&sS[d * DDIM + cbase];
            float qq[4] = {qf.x, qf.y, qf.z, qf.w};
            float ss[4] = {sf.x, sf.y, sf.z, sf.w};
            #pragma unroll
            for (int a = 0; a < 4; a++)
                #pragma unroll
                for (int b = 0; b < 4; b++)
                    acc[a][b] += qq[a] * ss[b];
        }
        const float* Pg = g_P + base;
        #pragma unroll
        for (int a = 0; a < 4; a++) {
            float4 pf = *(const float4*)&Pg[(size_t)(rbase + a) * DDIM + cbase];
            float inv = sDen[rbase + a];
            *(float4*)&Og[base + (size_t)(rbase + a) * DDIM + cbase] =
                make_float4((acc[a][0] + pf.x) * inv, (acc[a][1] + pf.y) * inv,
                            (acc[a][2] + pf.z) * inv, (acc[a][3] + pf.w) * inv);
        }
    }
}

// ---------------------------------------------------------------------------
extern "C" void kernel_launch(void* const* d_in, const int* in_sizes, int n_in,
                              void* d_out, int out_size) {
    const float* Q = (const float*)d_in[0];
    const float* K = (const float*)d_in[1];
    const float* V = (const float*)d_in[2];
    float* O = (float*)d_out;

    const int SMEMF = (2 * DDIM * ST + CHK * DDIM + CHK * ST) * (int)sizeof(float); // ~67.3 KB
    const int SMEME = (DDIM * ST + DDIM * DDIM + DDIM + CHK) * (int)sizeof(float);  // ~33.5 KB

    static int inited = 0;
    if (!inited) {
        cudaFuncSetAttribute(lin_fused, cudaFuncAttributeMaxDynamicSharedMemorySize, SMEMF);
        cudaFuncSetAttribute(lin_epi,   cudaFuncAttributeMaxDynamicSharedMemorySize, SMEME);
        inited = 1;
    }

    lin_fused<<<2 * NB, 256, SMEMF>>>(Q, K, V);
    lin_phase2<<<HNUM * 8, 512>>>();
    lin_epi<<<NB, 256, SMEME>>>(Q, O);
}

// round 8
// speedup vs baseline: 1.1086x; 1.1086x over previous
#include <cuda_runtime.h>

#define HNUM 16
#define NSEQ 2048
#define DDIM 64
#define CHK  64
#define NC   (NSEQ / CHK)      // 32 chunks
#define NB   (HNUM * NC)       // 512 (head, chunk) tiles
#define EPSV 1e-6f

#define ST 68                  // padded stride (68*4 bytes = 16B multiple)

typedef unsigned long long u64;

// Scratch: per-(head,chunk) KV state (64x64) and K feature-sum (64).
__device__ float g_KV[(size_t)NB * DDIM * DDIM];   // 8 MB
__device__ float g_Kz[(size_t)NB * DDIM];          // 128 KB

__device__ __forceinline__ float fmap(float x) {
    return x > 0.f ? x + 1.f : __expf(x);
}

// ---- packed fp32x2 helpers (sm_103a FFMA2 path, PTX-only) ----
__device__ __forceinline__ u64 bcast2(float x) {
    u64 r;
    asm("mov.b64 %0, {%1, %1};" : "=l"(r) : "r"(__float_as_uint(x)));
    return r;
}
__device__ __forceinline__ void ffma2(u64& d, u64 a, u64 b) {
    asm("fma.rn.f32x2 %0, %1, %2, %3;" : "=l"(d) : "l"(a), "l"(b), "l"(d));
}
__device__ __forceinline__ float2 unpack2(u64 v) {
    unsigned lo, hi;
    asm("mov.b64 {%0, %1}, %2;" : "=r"(lo), "=r"(hi) : "l"(v));
    return make_float2(__uint_as_float(lo), __uint_as_float(hi));
}

// ---------------------------------------------------------------------------
// Phase 1: per-chunk KV = phiK^T V  (64x64)  and Kz = colsum(phiK)
// grid = NB (512), block = 256.  Inner GEMM in f32x2.
// ---------------------------------------------------------------------------
__global__ void __launch_bounds__(256) lin_phase1(const float* __restrict__ Kg,
                                                  const float* __restrict__ Vg) {
    extern __shared__ float sm[];
    float* sK = sm;                    // CHK*DDIM
    float* sV = sm + CHK * DDIM;       // CHK*DDIM
    const int tid = threadIdx.x;
    const size_t base = (size_t)blockIdx.x * (CHK * DDIM);

    #pragma unroll
    for (int s = 0; s < 4; s++) {
        int i4 = tid + s * 256;
        float4 k = ((const float4*)(Kg + base))[i4];
        float4 v = ((const float4*)(Vg + base))[i4];
        k.x = fmap(k.x); k.y = fmap(k.y); k.z = fmap(k.z); k.w = fmap(k.w);
        ((float4*)sK)[i4] = k;
        ((float4*)sV)[i4] = v;
    }
    __syncthreads();

    const int d0 = (tid >> 4) * 4;
    const int e0 = (tid & 15) * 4;
    u64 acc2[4][2] = {};
    #pragma unroll 8
    for (int m = 0; m < CHK; m++) {
        float4 kf = *(const float4*)&sK[m * DDIM + d0];
        ulonglong2 vp = *(const ulonglong2*)&sV[m * DDIM + e0];
        float kk[4] = {kf.x, kf.y, kf.z, kf.w};
        #pragma unroll
        for (int a = 0; a < 4; a++) {
            u64 ka = bcast2(kk[a]);
            ffma2(acc2[a][0], ka, vp.x);
            ffma2(acc2[a][1], ka, vp.y);
        }
    }

    float* kvo = g_KV + (size_t)blockIdx.x * (DDIM * DDIM);
    #pragma unroll
    for (int a = 0; a < 4; a++) {
        float2 p0 = unpack2(acc2[a][0]);
        float2 p1 = unpack2(acc2[a][1]);
        *(float4*)&kvo[(d0 + a) * DDIM + e0] = make_float4(p0.x, p0.y, p1.x, p1.y);
    }

    if (tid < DDIM) {
        float s = 0.f;
        #pragma unroll 8
        for (int m = 0; m < CHK; m++) s += sK[m * DDIM + tid];
        g_Kz[(size_t)blockIdx.x * DDIM + tid] = s;
    }
}

// ---------------------------------------------------------------------------
// Phase 2: in-place exclusive prefix over 32 chunks (per head). [R2 verbatim]
// ---------------------------------------------------------------------------
__global__ void __launch_bounds__(512) lin_phase2() {
    const int h = blockIdx.x >> 3;
    const int part = blockIdx.x & 7;
    const int idx = part * 512 + threadIdx.x;

    float run = 0.f;
    #pragma unroll
    for (int c = 0; c < NC; c++) {
        float* p = g_KV + ((size_t)(h * NC + c)) * (DDIM * DDIM) + idx;
        float v = *p;
        *p = run;
        run += v;
    }
    if (part == 0 && threadIdx.x < DDIM) {
        float rz = 0.f;
        #pragma unroll
        for (int c = 0; c < NC; c++) {
            float* p = g_Kz + (size_t)(h * NC + c) * DDIM + threadIdx.x;
            float v = *p;
            *p = rz;
            rz += v;
        }
    }
}

// ---------------------------------------------------------------------------
// Phase 3 [R6 structure]: A = phiQ phiK^T (masked, transposed),
// den, out = (A@V + phiQ@S)/den.  All GEMM inner loops in f32x2.
// grid = NB (512), block = 256, 85.5 KB smem (2 CTAs/SM).
// ---------------------------------------------------------------------------
__global__ void __launch_bounds__(256) lin_phase3(const float* __restrict__ Qg,
                                                  const float* __restrict__ Kg,
                                                  const float* __restrict__ Vg,
                                                  float* __restrict__ Og) {
    extern __shared__ float sm[];
    float* sQt  = sm;                   // [d][m] DDIM*ST
    float* sKt  = sQt + DDIM * ST;      // [d][j] DDIM*ST
    float* sV   = sKt + DDIM * ST;      // [k][e] CHK*DDIM
    float* sS   = sV  + CHK * DDIM;     // [d][e] DDIM*DDIM
    float* sAt  = sS  + DDIM * DDIM;    // [k][m] CHK*ST
    float* sZ   = sAt + CHK * ST;       // DDIM
    float* sDen = sZ  + DDIM;           // CHK

    const int tid = threadIdx.x;
    const size_t base = (size_t)blockIdx.x * (CHK * DDIM);

    // --- load + feature map + transpose Q,K; V row-major; S,z ---
    {
        const int m  = tid >> 2;
        const int d0 = (tid & 3) * 16;
        #pragma unroll
        for (int u = 0; u < 4; u++) {
            int col = d0 + 4 * u;
            float4 q = *(const float4*)(Qg + base + m * DDIM + col);
            float4 k = *(const float4*)(Kg + base + m * DDIM + col);
            float4 v = *(const float4*)(Vg + base + m * DDIM + col);
            sQt[(col + 0) * ST + m] = fmap(q.x);
            sQt[(col + 1) * ST + m] = fmap(q.y);
            sQt[(col + 2) * ST + m] = fmap(q.z);
            sQt[(col + 3) * ST + m] = fmap(q.w);
            sKt[(col + 0) * ST + m] = fmap(k.x);
            sKt[(col + 1) * ST + m] = fmap(k.y);
            sKt[(col + 2) * ST + m] = fmap(k.z);
            sKt[(col + 3) * ST + m] = fmap(k.w);
            *(float4*)&sV[m * DDIM + col] = v;
        }
        const float4* Sg4 = (const float4*)(g_KV + (size_t)blockIdx.x * (DDIM * DDIM));
        #pragma unroll
        for (int s = 0; s < 4; s++)
            ((float4*)sS)[tid + s * 256] = Sg4[tid + s * 256];
        if (tid < DDIM) sZ[tid] = g_Kz[(size_t)blockIdx.x * DDIM + tid];
    }
    __syncthreads();

    // --- A-phase (f32x2): pairs over columns j ---
    {
        const int rbase = (tid >> 4) * 4;
        const int cbase = (tid & 15) * 4;
        u64 acc2[4][2] = {};
        #pragma unroll 8
        for (int d = 0; d < DDIM; d++) {
            float4 qf = *(const float4*)&sQt[d * ST + rbase];
            ulonglong2 kp = *(const ulonglong2*)&sKt[d * ST + cbase];
            float qq[4] = {qf.x, qf.y, qf.z, qf.w};
            #pragma unroll
            for (int a = 0; a < 4; a++) {
                u64 qa = bcast2(qq[a]);
                ffma2(acc2[a][0], qa, kp.x);
                ffma2(acc2[a][1], qa, kp.y);
            }
        }
        float accs[4][4];
        #pragma unroll
        for (int a = 0; a < 4; a++) {
            float2 p0 = unpack2(acc2[a][0]);
            float2 p1 = unpack2(acc2[a][1]);
            accs[a][0] = p0.x; accs[a][1] = p0.y;
            accs[a][2] = p1.x; accs[a][3] = p1.y;
        }
        #pragma unroll
        for (int b = 0; b < 4; b++) {
            int col = cbase + b;
            float4 o;
            o.x = (col <= rbase + 0) ? accs[0][b] : 0.f;
            o.y = (col <= rbase + 1) ? accs[1][b] : 0.f;
            o.z = (col <= rbase + 2) ? accs[2][b] : 0.f;
            o.w = (col <= rbase + 3) ? accs[3][b] : 0.f;
            *(float4*)&sAt[col * ST + rbase] = o;
        }
    }
    __syncthreads();

    // --- denominator ---
    if (tid < CHK) {
        float s = EPSV;
        #pragma unroll 8
        for (int k = 0; k < CHK; k++) s += sAt[k * ST + tid];
        #pragma unroll 8
        for (int d = 0; d < DDIM; d++) s += sQt[d * ST + tid] * sZ[d];
        sDen[tid] = 1.f / s;
    }
    __syncthreads();

    // --- B-phase (f32x2): balanced causal row-pairing [R6 structure] ---
    {
        const int w    = tid >> 5;
        const int half = (tid >> 4) & 1;
        const int cb   = (tid & 15) * 4;
        const int rL   = 4 * w + 2 * half;
        const int rH   = 60 - 4 * w + 2 * half;

        u64 accL[2][2] = {};   // [row i][col pair]
        u64 accH[2][2] = {};

        #pragma unroll
        for (int s = 0; s < 16; s++) {
            if (s < w + 1) {
                #pragma unroll
                for (int kk = 0; kk < 4; kk++) {
                    int k = s * 4 + kk;
                    float2 aL = *(const float2*)&sAt[k * ST + rL];
                    float2 aH = *(const float2*)&sAt[k * ST + rH];
                    ulonglong2 vp = *(const ulonglong2*)&sV[k * DDIM + cb];
                    u64 aL0 = bcast2(aL.x), aL1 = bcast2(aL.y);
                    u64 aH0 = bcast2(aH.x), aH1 = bcast2(aH.y);
                    ffma2(accL[0][0], aL0, vp.x); ffma2(accL[0][1], aL0, vp.y);
                    ffma2(accL[1][0], aL1, vp.x); ffma2(accL[1][1], aL1, vp.y);
                    ffma2(accH[0][0], aH0, vp.x); ffma2(accH[0][1], aH0, vp.y);
                    ffma2(accH[1][0], aH1, vp.x); ffma2(accH[1][1], aH1, vp.y);
                }
            } else if (s < 16 - w) {
                #pragma unroll
                for (int kk = 0; kk < 4; kk++) {
                    int k = s * 4 + kk;
                    float2 aH = *(const float2*)&sAt[k * ST + rH];
                    ulonglong2 vp = *(const ulonglong2*)&sV[k * DDIM + cb];
                    u64 aH0 = bcast2(aH.x), aH1 = bcast2(aH.y);
                    ffma2(accH[0][0], aH0, vp.x); ffma2(accH[0][1], aH0, vp.y);
                    ffma2(accH[1][0], aH1, vp.x); ffma2(accH[1][1], aH1, vp.y);
                }
            }
        }

        // Q@S: full
        #pragma unroll 8
        for (int d = 0; d < DDIM; d++) {
            float2 qL = *(const float2*)&sQt[d * ST + rL];
            float2 qH = *(const float2*)&sQt[d * ST + rH];
            ulonglong2 sp = *(const ulonglong2*)&sS[d * DDIM + cb];
            u64 qL0 = bcast2(qL.x), qL1 = bcast2(qL.y);
            u64 qH0 = bcast2(qH.x), qH1 = bcast2(qH.y);
            ffma2(accL[0][0], qL0, sp.x); ffma2(accL[0][1], qL0, sp.y);
            ffma2(accL[1][0], qL1, sp.x); ffma2(accL[1][1], qL1, sp.y);
            ffma2(accH[0][0], qH0, sp.x); ffma2(accH[0][1], qH0, sp.y);
            ffma2(accH[1][0], qH1, sp.x); ffma2(accH[1][1], qH1, sp.y);
        }

        #pragma unroll
        for (int i = 0; i < 2; i++) {
            float invL = sDen[rL + i];
            float2 l0 = unpack2(accL[i][0]);
            float2 l1 = unpack2(accL[i][1]);
            *(float4*)&Og[base + (size_t)(rL + i) * DDIM + cb] =
                make_float4(l0.x * invL, l0.y * invL, l1.x * invL, l1.y * invL);
            float invH = sDen[rH + i];
            float2 h0 = unpack2(accH[i][0]);
            float2 h1 = unpack2(accH[i][1]);
            *(float4*)&Og[base + (size_t)(rH + i) * DDIM + cb] =
                make_float4(h0.x * invH, h0.y * invH, h1.x * invH, h1.y * invH);
        }
    }
}

// ---------------------------------------------------------------------------
extern "C" void kernel_launch(void* const* d_in, const int* in_sizes, int n_in,
                              void* d_out, int out_size) {
    const float* Q = (const float*)d_in[0];
    const float* K = (const float*)d_in[1];
    const float* V = (const float*)d_in[2];
    float* O = (float*)d_out;

    const int SMEM1 = 2 * CHK * DDIM * (int)sizeof(float);                   // 32 KB
    const int SMEM3 = (2 * DDIM * ST + CHK * DDIM + DDIM * DDIM +
                       CHK * ST + DDIM + CHK) * (int)sizeof(float);          // ~85.5 KB

    static int inited = 0;
    if (!inited) {
        cudaFuncSetAttribute(lin_phase1, cudaFuncAttributeMaxDynamicSharedMemorySize, SMEM1);
        cudaFuncSetAttribute(lin_phase3, cudaFuncAttributeMaxDynamicSharedMemorySize, SMEM3);
        inited = 1;
    }

    lin_phase1<<<NB, 256, SMEM1>>>(K, V);
    lin_phase2<<<HNUM * 8, 512>>>();
    lin_phase3<<<NB, 256, SMEM3>>>(Q, K, V, O);
}

// round 9
// speedup vs baseline: 1.4714x; 1.3273x over previous
#include <cuda_runtime.h>
#include <cuda_bf16.h>
#include <cstdint>

#define HNUM 16
#define NSEQ 2048
#define DDIM 64
#define CHK  64
#define NC   (NSEQ / CHK)      // 32 chunks
#define NB   (HNUM * NC)       // 512 (head, chunk) tiles
#define EPSV 1e-6f

typedef unsigned long long u64;

// Scratch: per-(head,chunk) KV state (64x64) and K feature-sum (64).
__device__ float g_KV[(size_t)NB * DDIM * DDIM];   // 8 MB
__device__ float g_Kz[(size_t)NB * DDIM];          // 128 KB

__device__ __forceinline__ float fmap(float x) {
    return x > 0.f ? x + 1.f : __expf(x);
}

// ---- packed fp32x2 helpers (champion phase1) ----
__device__ __forceinline__ u64 bcast2(float x) {
    u64 r;
    asm("mov.b64 %0, {%1, %1};" : "=l"(r) : "r"(__float_as_uint(x)));
    return r;
}
__device__ __forceinline__ void ffma2(u64& d, u64 a, u64 b) {
    asm("fma.rn.f32x2 %0, %1, %2, %3;" : "=l"(d) : "l"(a), "l"(b), "l"(d));
}
__device__ __forceinline__ float2 unpack2(u64 v) {
    unsigned lo, hi;
    asm("mov.b64 {%0, %1}, %2;" : "=r"(lo), "=r"(hi) : "l"(v));
    return make_float2(__uint_as_float(lo), __uint_as_float(hi));
}

// ---- mma helpers ----
__device__ __forceinline__ uint32_t smem_u32(const void* p) {
    return (uint32_t)__cvta_generic_to_shared(p);
}
__device__ __forceinline__ void ldsm_x4(uint32_t a[4], uint32_t addr) {
    asm volatile("ldmatrix.sync.aligned.m8n8.x4.shared.b16 {%0,%1,%2,%3}, [%4];"
                 : "=r"(a[0]), "=r"(a[1]), "=r"(a[2]), "=r"(a[3]) : "r"(addr));
}
__device__ __forceinline__ void ldsm_x4t(uint32_t a[4], uint32_t addr) {
    asm volatile("ldmatrix.sync.aligned.m8n8.x4.trans.shared.b16 {%0,%1,%2,%3}, [%4];"
                 : "=r"(a[0]), "=r"(a[1]), "=r"(a[2]), "=r"(a[3]) : "r"(addr));
}
__device__ __forceinline__ void ldsm_x2t(uint32_t a[2], uint32_t addr) {
    asm volatile("ldmatrix.sync.aligned.m8n8.x2.trans.shared.b16 {%0,%1}, [%2];"
                 : "=r"(a[0]), "=r"(a[1]) : "r"(addr));
}
__device__ __forceinline__ void mma_bf16(float d[4], const uint32_t a[4],
                                         const uint32_t b0, const uint32_t b1) {
    asm volatile(
        "mma.sync.aligned.m16n8k16.row.col.f32.bf16.bf16.f32 "
        "{%0,%1,%2,%3}, {%4,%5,%6,%7}, {%8,%9}, {%0,%1,%2,%3};"
        : "+f"(d[0]), "+f"(d[1]), "+f"(d[2]), "+f"(d[3])
        : "r"(a[0]), "r"(a[1]), "r"(a[2]), "r"(a[3]), "r"(b0), "r"(b1));
}
__device__ __forceinline__ void splitb(float x, __nv_bfloat16& h, __nv_bfloat16& l) {
    h = __float2bfloat16(x);
    l = __float2bfloat16(x - __bfloat162float(h));
}

// ---------------------------------------------------------------------------
// Phase 1: per-chunk KV = phiK^T V and Kz = colsum(phiK)  [R8 champion]
// ---------------------------------------------------------------------------
__global__ void __launch_bounds__(256) lin_phase1(const float* __restrict__ Kg,
                                                  const float* __restrict__ Vg) {
    extern __shared__ float sm[];
    float* sK = sm;
    float* sV = sm + CHK * DDIM;
    const int tid = threadIdx.x;
    const size_t base = (size_t)blockIdx.x * (CHK * DDIM);

    #pragma unroll
    for (int s = 0; s < 4; s++) {
        int i4 = tid + s * 256;
        float4 k = ((const float4*)(Kg + base))[i4];
        float4 v = ((const float4*)(Vg + base))[i4];
        k.x = fmap(k.x); k.y = fmap(k.y); k.z = fmap(k.z); k.w = fmap(k.w);
        ((float4*)sK)[i4] = k;
        ((float4*)sV)[i4] = v;
    }
    __syncthreads();

    const int d0 = (tid >> 4) * 4;
    const int e0 = (tid & 15) * 4;
    u64 acc2[4][2] = {};
    #pragma unroll 8
    for (int m = 0; m < CHK; m++) {
        float4 kf = *(const float4*)&sK[m * DDIM + d0];
        ulonglong2 vp = *(const ulonglong2*)&sV[m * DDIM + e0];
        float kk[4] = {kf.x, kf.y, kf.z, kf.w};
        #pragma unroll
        for (int a = 0; a < 4; a++) {
            u64 ka = bcast2(kk[a]);
            ffma2(acc2[a][0], ka, vp.x);
            ffma2(acc2[a][1], ka, vp.y);
        }
    }

    float* kvo = g_KV + (size_t)blockIdx.x * (DDIM * DDIM);
    #pragma unroll
    for (int a = 0; a < 4; a++) {
        float2 p0 = unpack2(acc2[a][0]);
        float2 p1 = unpack2(acc2[a][1]);
        *(float4*)&kvo[(d0 + a) * DDIM + e0] = make_float4(p0.x, p0.y, p1.x, p1.y);
    }

    if (tid < DDIM) {
        float s = 0.f;
        #pragma unroll 8
        for (int m = 0; m < CHK; m++) s += sK[m * DDIM + tid];
        g_Kz[(size_t)blockIdx.x * DDIM + tid] = s;
    }
}

// ---------------------------------------------------------------------------
// Phase 2: exclusive prefix over 32 chunks per head. [champion]
// ---------------------------------------------------------------------------
__global__ void __launch_bounds__(512) lin_phase2() {
    const int h = blockIdx.x >> 3;
    const int part = blockIdx.x & 7;
    const int idx = part * 512 + threadIdx.x;

    float run = 0.f;
    #pragma unroll
    for (int c = 0; c < NC; c++) {
        float* p = g_KV + ((size_t)(h * NC + c)) * (DDIM * DDIM) + idx;
        float v = *p;
        *p = run;
        run += v;
    }
    if (part == 0 && threadIdx.x < DDIM) {
        float rz = 0.f;
        #pragma unroll
        for (int c = 0; c < NC; c++) {
            float* p = g_Kz + (size_t)(h * NC + c) * DDIM + threadIdx.x;
            float v = *p;
            *p = rz;
            rz += v;
        }
    }
}

// ---------------------------------------------------------------------------
// Phase 3: tensor-core (bf16-split mma.sync).
// smem: 10 bf16 tiles [64][72] (Qh,Ql,Kh,Kl,Vh,Vl,Sh,Sl,Ah,Al) + sDen[64].
// Aux column 64: V=1, S=z  => B-phase col 64 = rowsum(A)+qz = denominator.
// grid = NB (512), block = 256 (8 warps, 4x2 tile grid of m16n8).
// ---------------------------------------------------------------------------
#define ST2 72
#define TILE_ELEMS (64 * ST2)

__global__ void __launch_bounds__(256) lin_phase3(const float* __restrict__ Qg,
                                                  const float* __restrict__ Kg,
                                                  const float* __restrict__ Vg,
                                                  float* __restrict__ Og) {
    extern __shared__ __nv_bfloat16 smb[];
    __nv_bfloat16* sQh = smb;
    __nv_bfloat16* sQl = sQh + TILE_ELEMS;
    __nv_bfloat16* sKh = sQl + TILE_ELEMS;   // [d][j] = phiK^T
    __nv_bfloat16* sKl = sKh + TILE_ELEMS;
    __nv_bfloat16* sVh = sKl + TILE_ELEMS;   // [k][e], col64 = 1
    __nv_bfloat16* sVl = sVh + TILE_ELEMS;
    __nv_bfloat16* sSh = sVl + TILE_ELEMS;   // [d][e], col64 = z
    __nv_bfloat16* sSl = sSh + TILE_ELEMS;
    __nv_bfloat16* sAh = sSl + TILE_ELEMS;   // [m][k] masked A
    __nv_bfloat16* sAl = sAh + TILE_ELEMS;
    float* sDen = (float*)(sAl + TILE_ELEMS);

    const int tid = threadIdx.x;
    const size_t base = (size_t)blockIdx.x * (CHK * DDIM);

    // ---------------- load + fmap + split ----------------
    {
        const int m  = tid >> 2;          // 0..63
        const int c0 = (tid & 3) * 16;
        #pragma unroll
        for (int u = 0; u < 4; u++) {
            int col = c0 + 4 * u;
            float4 q = *(const float4*)(Qg + base + m * DDIM + col);
            float4 k = *(const float4*)(Kg + base + m * DDIM + col);
            float4 v = *(const float4*)(Vg + base + m * DDIM + col);
            float qv[4] = {fmap(q.x), fmap(q.y), fmap(q.z), fmap(q.w)};
            float kv[4] = {fmap(k.x), fmap(k.y), fmap(k.z), fmap(k.w)};
            float vv[4] = {v.x, v.y, v.z, v.w};
            #pragma unroll
            for (int p = 0; p < 2; p++) {
                __nv_bfloat162 qh2, ql2, vh2, vl2;
                splitb(qv[2*p],   qh2.x, ql2.x);
                splitb(qv[2*p+1], qh2.y, ql2.y);
                splitb(vv[2*p],   vh2.x, vl2.x);
                splitb(vv[2*p+1], vh2.y, vl2.y);
                *(__nv_bfloat162*)&sQh[m * ST2 + col + 2*p] = qh2;
                *(__nv_bfloat162*)&sQl[m * ST2 + col + 2*p] = ql2;
                *(__nv_bfloat162*)&sVh[m * ST2 + col + 2*p] = vh2;
                *(__nv_bfloat162*)&sVl[m * ST2 + col + 2*p] = vl2;
            }
            #pragma unroll
            for (int p = 0; p < 4; p++) {               // K transposed
                __nv_bfloat16 h, l;
                splitb(kv[p], h, l);
                sKh[(col + p) * ST2 + m] = h;
                sKl[(col + p) * ST2 + m] = l;
            }
        }
        // S from scan scratch
        const float4* Sg4 = (const float4*)(g_KV + (size_t)blockIdx.x * (DDIM * DDIM));
        #pragma unroll
        for (int s = 0; s < 4; s++) {
            int i4 = tid + s * 256;
            int d  = i4 >> 4;
            int e0 = (i4 & 15) * 4;
            float4 sv = Sg4[i4];
            float ss[4] = {sv.x, sv.y, sv.z, sv.w};
            #pragma unroll
            for (int p = 0; p < 2; p++) {
                __nv_bfloat162 h2, l2;
                splitb(ss[2*p],   h2.x, l2.x);
                splitb(ss[2*p+1], h2.y, l2.y);
                *(__nv_bfloat162*)&sSh[d * ST2 + e0 + 2*p] = h2;
                *(__nv_bfloat162*)&sSl[d * ST2 + e0 + 2*p] = l2;
            }
        }
        // aux columns 64..71
        if (tid < 64) {
            float z = g_Kz[(size_t)blockIdx.x * DDIM + tid];
            __nv_bfloat16 zh, zl;
            splitb(z, zh, zl);
            sSh[tid * ST2 + 64] = zh;
            sSl[tid * ST2 + 64] = zl;
            sVh[tid * ST2 + 64] = __float2bfloat16(1.0f);
            sVl[tid * ST2 + 64] = __float2bfloat16(0.0f);
            #pragma unroll
            for (int c = 65; c < 72; c++) {
                sVh[tid * ST2 + c] = __float2bfloat16(0.0f);
                sVl[tid * ST2 + c] = __float2bfloat16(0.0f);
                sSh[tid * ST2 + c] = __float2bfloat16(0.0f);
                sSl[tid * ST2 + c] = __float2bfloat16(0.0f);
            }
        }
    }
    __syncthreads();

    const int w    = tid >> 5;
    const int lane = tid & 31;
    const int g    = lane >> 2;
    const int tig  = lane & 3;
    const int mrow = (w >> 1) * 16;
    const int jcol = (w & 1) * 32;
    // ldmatrix lane-address components
    const int lr  = lane & 7;
    const int lhf = (lane >> 3) & 1;
    const int lnh = lane >> 4;

    // ---------------- A-phase: A = phiQ phiK^T ----------------
    {
        float dA[4][4] = {};
        #pragma unroll
        for (int ks = 0; ks < 4; ks++) {
            uint32_t ah[4], al[4];
            {
                uint32_t addr = smem_u32(&sQh[(mrow + lhf*8 + lr) * ST2 + ks*16 + lnh*8]);
                ldsm_x4(ah, addr);
                addr = smem_u32(&sQl[(mrow + lhf*8 + lr) * ST2 + ks*16 + lnh*8]);
                ldsm_x4(al, addr);
            }
            uint32_t bh[4][2], bl[4][2];
            #pragma unroll
            for (int blk = 0; blk < 2; blk++) {      // 16 cols per block
                uint32_t r4[4];
                uint32_t addr = smem_u32(&sKh[(ks*16 + lhf*8 + lr) * ST2 + jcol + blk*16 + lnh*8]);
                ldsm_x4t(r4, addr);
                bh[blk*2][0] = r4[0]; bh[blk*2][1] = r4[1];
                bh[blk*2+1][0] = r4[2]; bh[blk*2+1][1] = r4[3];
                addr = smem_u32(&sKl[(ks*16 + lhf*8 + lr) * ST2 + jcol + blk*16 + lnh*8]);
                ldsm_x4t(r4, addr);
                bl[blk*2][0] = r4[0]; bl[blk*2][1] = r4[1];
                bl[blk*2+1][0] = r4[2]; bl[blk*2+1][1] = r4[3];
            }
            #pragma unroll
            for (int t = 0; t < 4; t++) {
                mma_bf16(dA[t], ah, bh[t][0], bh[t][1]);
                mma_bf16(dA[t], ah, bl[t][0], bl[t][1]);
                mma_bf16(dA[t], al, bh[t][0], bh[t][1]);
            }
        }
        // mask + store bf16 hi/lo
        const int row0 = mrow + g;
        const int row1 = row0 + 8;
        #pragma unroll
        for (int t = 0; t < 4; t++) {
            int col = jcol + 8*t + 2*tig;
            float c0 = (col     <= row0) ? dA[t][0] : 0.f;
            float c1 = (col + 1 <= row0) ? dA[t][1] : 0.f;
            float c2 = (col     <= row1) ? dA[t][2] : 0.f;
            float c3 = (col + 1 <= row1) ? dA[t][3] : 0.f;
            __nv_bfloat162 h2, l2;
            splitb(c0, h2.x, l2.x); splitb(c1, h2.y, l2.y);
            *(__nv_bfloat162*)&sAh[row0 * ST2 + col] = h2;
            *(__nv_bfloat162*)&sAl[row0 * ST2 + col] = l2;
            splitb(c2, h2.x, l2.x); splitb(c3, h2.y, l2.y);
            *(__nv_bfloat162*)&sAh[row1 * ST2 + col] = h2;
            *(__nv_bfloat162*)&sAl[row1 * ST2 + col] = l2;
        }
    }
    __syncthreads();

    // ---------------- B-phase: out = A@V + phiQ@S (+aux den col) ----------------
    {
        const bool has_aux = (w & 1);            // col group 1 also owns cols 64-71
        float dO[5][4] = {};

        #pragma unroll
        for (int gsel = 0; gsel < 2; gsel++) {   // 0: A@V, 1: Q@S
            const __nv_bfloat16* Aoph = gsel ? sQh : sAh;
            const __nv_bfloat16* Aopl = gsel ? sQl : sAl;
            const __nv_bfloat16* Boph = gsel ? sSh : sVh;
            const __nv_bfloat16* Bopl = gsel ? sSl : sVl;
            #pragma unroll
            for (int ks = 0; ks < 4; ks++) {
                uint32_t ah[4], al[4];
                ldsm_x4(ah, smem_u32(&Aoph[(mrow + lhf*8 + lr) * ST2 + ks*16 + lnh*8]));
                ldsm_x4(al, smem_u32(&Aopl[(mrow + lhf*8 + lr) * ST2 + ks*16 + lnh*8]));
                uint32_t bh[4][2], bl[4][2];
                #pragma unroll
                for (int blk = 0; blk < 2; blk++) {
                    uint32_t r4[4];
                    ldsm_x4t(r4, smem_u32(&Boph[(ks*16 + lhf*8 + lr) * ST2 + jcol + blk*16 + lnh*8]));
                    bh[blk*2][0] = r4[0]; bh[blk*2][1] = r4[1];
                    bh[blk*2+1][0] = r4[2]; bh[blk*2+1][1] = r4[3];
                    ldsm_x4t(r4, smem_u32(&Bopl[(ks*16 + lhf*8 + lr) * ST2 + jcol + blk*16 + lnh*8]));
                    bl[blk*2][0] = r4[0]; bl[blk*2][1] = r4[1];
                    bl[blk*2+1][0] = r4[2]; bl[blk*2+1][1] = r4[3];
                }
                #pragma unroll
                for (int t = 0; t < 4; t++) {
                    mma_bf16(dO[t], ah, bh[t][0], bh[t][1]);
                    mma_bf16(dO[t], ah, bl[t][0], bl[t][1]);
                    mma_bf16(dO[t], al, bh[t][0], bh[t][1]);
                }
                if (has_aux) {                    // cols 64-71
                    uint32_t bxh[2], bxl[2];
                    int r16 = lane & 15;
                    int rr  = (r16 & 7) + ((r16 >> 3) & 1) * 8;
                    ldsm_x2t(bxh, smem_u32(&Boph[(ks*16 + rr) * ST2 + 64]));
                    ldsm_x2t(bxl, smem_u32(&Bopl[(ks*16 + rr) * ST2 + 64]));
                    mma_bf16(dO[4], ah, bxh[0], bxh[1]);
                    mma_bf16(dO[4], ah, bxl[0], bxl[1]);
                    mma_bf16(dO[4], al, bxh[0], bxh[1]);
                }
            }
        }

        const int row0 = mrow + g;
        const int row1 = row0 + 8;

        if (has_aux && tig == 0) {               // col 64 = den (rowsum + qz)
            sDen[row0] = 1.f / (dO[4][0] + EPSV);
            sDen[row1] = 1.f / (dO[4][2] + EPSV);
        }
        __syncthreads();

        const float inv0 = sDen[row0];
        const float inv1 = sDen[row1];
        #pragma unroll
        for (int t = 0; t < 4; t++) {
            int col = jcol + 8*t + 2*tig;
            *(float2*)&Og[base + (size_t)row0 * DDIM + col] =
                make_float2(dO[t][0] * inv0, dO[t][1] * inv0);
            *(float2*)&Og[base + (size_t)row1 * DDIM + col] =
                make_float2(dO[t][2] * inv1, dO[t][3] * inv1);
        }
    }
}

// ---------------------------------------------------------------------------
extern "C" void kernel_launch(void* const* d_in, const int* in_sizes, int n_in,
                              void* d_out, int out_size) {
    const float* Q = (const float*)d_in[0];
    const float* K = (const float*)d_in[1];
    const float* V = (const float*)d_in[2];
    float* O = (float*)d_out;

    const int SMEM1 = 2 * CHK * DDIM * (int)sizeof(float);            // 32 KB
    const int SMEM3 = 10 * TILE_ELEMS * 2 + 64 * (int)sizeof(float);  // ~92.4 KB

    static int inited = 0;
    if (!inited) {
        cudaFuncSetAttribute(lin_phase1, cudaFuncAttributeMaxDynamicSharedMemorySize, SMEM1);
        cudaFuncSetAttribute(lin_phase3, cudaFuncAttributeMaxDynamicSharedMemorySize, SMEM3);
        inited = 1;
    }

    lin_phase1<<<NB, 256, SMEM1>>>(K, V);
    lin_phase2<<<HNUM * 8, 512>>>();
    lin_phase3<<<NB, 256, SMEM3>>>(Q, K, V, O);
}

// round 10
// speedup vs baseline: 1.5606x; 1.0606x over previous
#include <cuda_runtime.h>
#include <cuda_bf16.h>
#include <cstdint>

#define HNUM 16
#define NSEQ 2048
#define DDIM 64
#define CHK  64
#define NC   (NSEQ / CHK)      // 32 chunks
#define NB   (HNUM * NC)       // 512 (head, chunk) tiles
#define EPSV 1e-6f

// Scratch: per-(head,chunk) KV state (64x64) and K feature-sum (64).
__device__ float g_KV[(size_t)NB * DDIM * DDIM];   // 8 MB
__device__ float g_Kz[(size_t)NB * DDIM];          // 128 KB

__device__ __forceinline__ float fmap(float x) {
    return x > 0.f ? x + 1.f : __expf(x);
}

// ---- mma helpers ----
__device__ __forceinline__ uint32_t smem_u32(const void* p) {
    return (uint32_t)__cvta_generic_to_shared(p);
}
__device__ __forceinline__ void ldsm_x4(uint32_t a[4], uint32_t addr) {
    asm volatile("ldmatrix.sync.aligned.m8n8.x4.shared.b16 {%0,%1,%2,%3}, [%4];"
                 : "=r"(a[0]), "=r"(a[1]), "=r"(a[2]), "=r"(a[3]) : "r"(addr));
}
__device__ __forceinline__ void ldsm_x4t(uint32_t a[4], uint32_t addr) {
    asm volatile("ldmatrix.sync.aligned.m8n8.x4.trans.shared.b16 {%0,%1,%2,%3}, [%4];"
                 : "=r"(a[0]), "=r"(a[1]), "=r"(a[2]), "=r"(a[3]) : "r"(addr));
}
__device__ __forceinline__ void ldsm_x2t(uint32_t a[2], uint32_t addr) {
    asm volatile("ldmatrix.sync.aligned.m8n8.x2.trans.shared.b16 {%0,%1}, [%2];"
                 : "=r"(a[0]), "=r"(a[1]) : "r"(addr));
}
__device__ __forceinline__ void mma_bf16(float d[4], const uint32_t a[4],
                                         const uint32_t b0, const uint32_t b1) {
    asm volatile(
        "mma.sync.aligned.m16n8k16.row.col.f32.bf16.bf16.f32 "
        "{%0,%1,%2,%3}, {%4,%5,%6,%7}, {%8,%9}, {%0,%1,%2,%3};"
        : "+f"(d[0]), "+f"(d[1]), "+f"(d[2]), "+f"(d[3])
        : "r"(a[0]), "r"(a[1]), "r"(a[2]), "r"(a[3]), "r"(b0), "r"(b1));
}
__device__ __forceinline__ void splitb(float x, __nv_bfloat16& h, __nv_bfloat16& l) {
    h = __float2bfloat16(x);
    l = __float2bfloat16(x - __bfloat162float(h));
}

#define ST2 72
#define TILE_ELEMS (64 * ST2)

// ---------------------------------------------------------------------------
// Phase 1 (tensor-core): KV[d][e] = sum_m phiK[m][d] V[m][e]; aux col V[:,64]=1
// gives col 64 = Kz[d].  grid = NB (512), block = 256 (8 warps, 4x2 m16n8 grid).
// smem: sKt(h/l) [d][m], sV(h/l) [m][e(+aux)]  = 36 KB.
// ---------------------------------------------------------------------------
__global__ void __launch_bounds__(256) lin_phase1(const float* __restrict__ Kg,
                                                  const float* __restrict__ Vg) {
    extern __shared__ __nv_bfloat16 smb1[];
    __nv_bfloat16* sKth = smb1;                    // [d][m]
    __nv_bfloat16* sKtl = sKth + TILE_ELEMS;
    __nv_bfloat16* sVh  = sKtl + TILE_ELEMS;       // [m][e], col64 = 1
    __nv_bfloat16* sVl  = sVh  + TILE_ELEMS;

    const int tid = threadIdx.x;
    const size_t base = (size_t)blockIdx.x * (CHK * DDIM);

    // ---- load + fmap + split ----
    {
        const int m  = tid >> 2;          // 0..63
        const int c0 = (tid & 3) * 16;
        #pragma unroll
        for (int u = 0; u < 4; u++) {
            int col = c0 + 4 * u;
            float4 k = *(const float4*)(Kg + base + m * DDIM + col);
            float4 v = *(const float4*)(Vg + base + m * DDIM + col);
            float kv[4] = {fmap(k.x), fmap(k.y), fmap(k.z), fmap(k.w)};
            float vv[4] = {v.x, v.y, v.z, v.w};
            #pragma unroll
            for (int p = 0; p < 2; p++) {
                __nv_bfloat162 vh2, vl2;
                splitb(vv[2*p],   vh2.x, vl2.x);
                splitb(vv[2*p+1], vh2.y, vl2.y);
                *(__nv_bfloat162*)&sVh[m * ST2 + col + 2*p] = vh2;
                *(__nv_bfloat162*)&sVl[m * ST2 + col + 2*p] = vl2;
            }
            #pragma unroll
            for (int p = 0; p < 4; p++) {          // K transposed
                __nv_bfloat16 h, l;
                splitb(kv[p], h, l);
                sKth[(col + p) * ST2 + m] = h;
                sKtl[(col + p) * ST2 + m] = l;
            }
        }
        if (tid < 64) {                            // aux cols 64..71 of V
            sVh[tid * ST2 + 64] = __float2bfloat16(1.0f);
            sVl[tid * ST2 + 64] = __float2bfloat16(0.0f);
            #pragma unroll
            for (int c = 65; c < 72; c++) {
                sVh[tid * ST2 + c] = __float2bfloat16(0.0f);
                sVl[tid * ST2 + c] = __float2bfloat16(0.0f);
            }
        }
    }
    __syncthreads();

    const int w    = tid >> 5;
    const int lane = tid & 31;
    const int g    = lane >> 2;
    const int tig  = lane & 3;
    const int drow = (w >> 1) * 16;      // output row block (d)
    const int ecol = (w & 1) * 32;       // output col block (e)
    const int lr   = lane & 7;
    const int lhf  = (lane >> 3) & 1;
    const int lnh  = lane >> 4;
    const bool has_aux = (w & 1);

    float dO[5][4] = {};
    #pragma unroll
    for (int ks = 0; ks < 4; ks++) {     // k over m
        uint32_t ah[4], al[4];
        ldsm_x4(ah, smem_u32(&sKth[(drow + lhf*8 + lr) * ST2 + ks*16 + lnh*8]));
        ldsm_x4(al, smem_u32(&sKtl[(drow + lhf*8 + lr) * ST2 + ks*16 + lnh*8]));
        uint32_t bh[4][2], bl[4][2];
        #pragma unroll
        for (int blk = 0; blk < 2; blk++) {
            uint32_t r4[4];
            ldsm_x4t(r4, smem_u32(&sVh[(ks*16 + lhf*8 + lr) * ST2 + ecol + blk*16 + lnh*8]));
            bh[blk*2][0] = r4[0]; bh[blk*2][1] = r4[1];
            bh[blk*2+1][0] = r4[2]; bh[blk*2+1][1] = r4[3];
            ldsm_x4t(r4, smem_u32(&sVl[(ks*16 + lhf*8 + lr) * ST2 + ecol + blk*16 + lnh*8]));
            bl[blk*2][0] = r4[0]; bl[blk*2][1] = r4[1];
            bl[blk*2+1][0] = r4[2]; bl[blk*2+1][1] = r4[3];
        }
        #pragma unroll
        for (int t = 0; t < 4; t++) {
            mma_bf16(dO[t], ah, bh[t][0], bh[t][1]);
            mma_bf16(dO[t], ah, bl[t][0], bl[t][1]);
            mma_bf16(dO[t], al, bh[t][0], bh[t][1]);
        }
        if (has_aux) {
            uint32_t bxh[2], bxl[2];
            int r16 = lane & 15;
            int rr  = (r16 & 7) + ((r16 >> 3) & 1) * 8;
            ldsm_x2t(bxh, smem_u32(&sVh[(ks*16 + rr) * ST2 + 64]));
            ldsm_x2t(bxl, smem_u32(&sVl[(ks*16 + rr) * ST2 + 64]));
            mma_bf16(dO[4], ah, bxh[0], bxh[1]);
            mma_bf16(dO[4], ah, bxl[0], bxl[1]);
            mma_bf16(dO[4], al, bxh[0], bxh[1]);
        }
    }

    // write KV (fp32) and Kz
    float* kvo = g_KV + (size_t)blockIdx.x * (DDIM * DDIM);
    const int row0 = drow + g;
    const int row1 = row0 + 8;
    #pragma unroll
    for (int t = 0; t < 4; t++) {
        int col = ecol + 8*t + 2*tig;
        *(float2*)&kvo[row0 * DDIM + col] = make_float2(dO[t][0], dO[t][1]);
        *(float2*)&kvo[row1 * DDIM + col] = make_float2(dO[t][2], dO[t][3]);
    }
    if (has_aux && tig == 0) {
        g_Kz[(size_t)blockIdx.x * DDIM + row0] = dO[4][0];
        g_Kz[(size_t)blockIdx.x * DDIM + row1] = dO[4][2];
    }
}

// ---------------------------------------------------------------------------
// Phase 2: exclusive prefix over 32 chunks per head. [champion verbatim]
// ---------------------------------------------------------------------------
__global__ void __launch_bounds__(512) lin_phase2() {
    const int h = blockIdx.x >> 3;
    const int part = blockIdx.x & 7;
    const int idx = part * 512 + threadIdx.x;

    float run = 0.f;
    #pragma unroll
    for (int c = 0; c < NC; c++) {
        float* p = g_KV + ((size_t)(h * NC + c)) * (DDIM * DDIM) + idx;
        float v = *p;
        *p = run;
        run += v;
    }
    if (part == 0 && threadIdx.x < DDIM) {
        float rz = 0.f;
        #pragma unroll
        for (int c = 0; c < NC; c++) {
            float* p = g_Kz + (size_t)(h * NC + c) * DDIM + threadIdx.x;
            float v = *p;
            *p = rz;
            rz += v;
        }
    }
}

// ---------------------------------------------------------------------------
// Phase 3: tensor-core (bf16-split mma.sync). [R9 champion verbatim]
// ---------------------------------------------------------------------------
__global__ void __launch_bounds__(256) lin_phase3(const float* __restrict__ Qg,
                                                  const float* __restrict__ Kg,
                                                  const float* __restrict__ Vg,
                                                  float* __restrict__ Og) {
    extern __shared__ __nv_bfloat16 smb[];
    __nv_bfloat16* sQh = smb;
    __nv_bfloat16* sQl = sQh + TILE_ELEMS;
    __nv_bfloat16* sKh = sQl + TILE_ELEMS;   // [d][j] = phiK^T
    __nv_bfloat16* sKl = sKh + TILE_ELEMS;
    __nv_bfloat16* sVh = sKl + TILE_ELEMS;   // [k][e], col64 = 1
    __nv_bfloat16* sVl = sVh + TILE_ELEMS;
    __nv_bfloat16* sSh = sVl + TILE_ELEMS;   // [d][e], col64 = z
    __nv_bfloat16* sSl = sSh + TILE_ELEMS;
    __nv_bfloat16* sAh = sSl + TILE_ELEMS;   // [m][k] masked A
    __nv_bfloat16* sAl = sAh + TILE_ELEMS;
    float* sDen = (float*)(sAl + TILE_ELEMS);

    const int tid = threadIdx.x;
    const size_t base = (size_t)blockIdx.x * (CHK * DDIM);

    // ---------------- load + fmap + split ----------------
    {
        const int m  = tid >> 2;          // 0..63
        const int c0 = (tid & 3) * 16;
        #pragma unroll
        for (int u = 0; u < 4; u++) {
            int col = c0 + 4 * u;
            float4 q = *(const float4*)(Qg + base + m * DDIM + col);
            float4 k = *(const float4*)(Kg + base + m * DDIM + col);
            float4 v = *(const float4*)(Vg + base + m * DDIM + col);
            float qv[4] = {fmap(q.x), fmap(q.y), fmap(q.z), fmap(q.w)};
            float kv[4] = {fmap(k.x), fmap(k.y), fmap(k.z), fmap(k.w)};
            float vv[4] = {v.x, v.y, v.z, v.w};
            #pragma unroll
            for (int p = 0; p < 2; p++) {
                __nv_bfloat162 qh2, ql2, vh2, vl2;
                splitb(qv[2*p],   qh2.x, ql2.x);
                splitb(qv[2*p+1], qh2.y, ql2.y);
                splitb(vv[2*p],   vh2.x, vl2.x);
                splitb(vv[2*p+1], vh2.y, vl2.y);
                *(__nv_bfloat162*)&sQh[m * ST2 + col + 2*p] = qh2;
                *(__nv_bfloat162*)&sQl[m * ST2 + col + 2*p] = ql2;
                *(__nv_bfloat162*)&sVh[m * ST2 + col + 2*p] = vh2;
                *(__nv_bfloat162*)&sVl[m * ST2 + col + 2*p] = vl2;
            }
            #pragma unroll
            for (int p = 0; p < 4; p++) {               // K transposed
                __nv_bfloat16 h, l;
                splitb(kv[p], h, l);
                sKh[(col + p) * ST2 + m] = h;
                sKl[(col + p) * ST2 + m] = l;
            }
        }
        const float4* Sg4 = (const float4*)(g_KV + (size_t)blockIdx.x * (DDIM * DDIM));
        #pragma unroll
        for (int s = 0; s < 4; s++) {
            int i4 = tid + s * 256;
            int d  = i4 >> 4;
            int e0 = (i4 & 15) * 4;
            float4 sv = Sg4[i4];
            float ss[4] = {sv.x, sv.y, sv.z, sv.w};
            #pragma unroll
            for (int p = 0; p < 2; p++) {
                __nv_bfloat162 h2, l2;
                splitb(ss[2*p],   h2.x, l2.x);
                splitb(ss[2*p+1], h2.y, l2.y);
                *(__nv_bfloat162*)&sSh[d * ST2 + e0 + 2*p] = h2;
                *(__nv_bfloat162*)&sSl[d * ST2 + e0 + 2*p] = l2;
            }
        }
        if (tid < 64) {
            float z = g_Kz[(size_t)blockIdx.x * DDIM + tid];
            __nv_bfloat16 zh, zl;
            splitb(z, zh, zl);
            sSh[tid * ST2 + 64] = zh;
            sSl[tid * ST2 + 64] = zl;
            sVh[tid * ST2 + 64] = __float2bfloat16(1.0f);
            sVl[tid * ST2 + 64] = __float2bfloat16(0.0f);
            #pragma unroll
            for (int c = 65; c < 72; c++) {
                sVh[tid * ST2 + c] = __float2bfloat16(0.0f);
                sVl[tid * ST2 + c] = __float2bfloat16(0.0f);
                sSh[tid * ST2 + c] = __float2bfloat16(0.0f);
                sSl[tid * ST2 + c] = __float2bfloat16(0.0f);
            }
        }
    }
    __syncthreads();

    const int w    = tid >> 5;
    const int lane = tid & 31;
    const int g    = lane >> 2;
    const int tig  = lane & 3;
    const int mrow = (w >> 1) * 16;
    const int jcol = (w & 1) * 32;
    const int lr  = lane & 7;
    const int lhf = (lane >> 3) & 1;
    const int lnh = lane >> 4;

    // ---------------- A-phase ----------------
    {
        float dA[4][4] = {};
        #pragma unroll
        for (int ks = 0; ks < 4; ks++) {
            uint32_t ah[4], al[4];
            ldsm_x4(ah, smem_u32(&sQh[(mrow + lhf*8 + lr) * ST2 + ks*16 + lnh*8]));
            ldsm_x4(al, smem_u32(&sQl[(mrow + lhf*8 + lr) * ST2 + ks*16 + lnh*8]));
            uint32_t bh[4][2], bl[4][2];
            #pragma unroll
            for (int blk = 0; blk < 2; blk++) {
                uint32_t r4[4];
                ldsm_x4t(r4, smem_u32(&sKh[(ks*16 + lhf*8 + lr) * ST2 + jcol + blk*16 + lnh*8]));
                bh[blk*2][0] = r4[0]; bh[blk*2][1] = r4[1];
                bh[blk*2+1][0] = r4[2]; bh[blk*2+1][1] = r4[3];
                ldsm_x4t(r4, smem_u32(&sKl[(ks*16 + lhf*8 + lr) * ST2 + jcol + blk*16 + lnh*8]));
                bl[blk*2][0] = r4[0]; bl[blk*2][1] = r4[1];
                bl[blk*2+1][0] = r4[2]; bl[blk*2+1][1] = r4[3];
            }
            #pragma unroll
            for (int t = 0; t < 4; t++) {
                mma_bf16(dA[t], ah, bh[t][0], bh[t][1]);
                mma_bf16(dA[t], ah, bl[t][0], bl[t][1]);
                mma_bf16(dA[t], al, bh[t][0], bh[t][1]);
            }
        }
        const int row0 = mrow + g;
        const int row1 = row0 + 8;
        #pragma unroll
        for (int t = 0; t < 4; t++) {
            int col = jcol + 8*t + 2*tig;
            float c0 = (col     <= row0) ? dA[t][0] : 0.f;
            float c1 = (col + 1 <= row0) ? dA[t][1] : 0.f;
            float c2 = (col     <= row1) ? dA[t][2] : 0.f;
            float c3 = (col + 1 <= row1) ? dA[t][3] : 0.f;
            __nv_bfloat162 h2, l2;
            splitb(c0, h2.x, l2.x); splitb(c1, h2.y, l2.y);
            *(__nv_bfloat162*)&sAh[row0 * ST2 + col] = h2;
            *(__nv_bfloat162*)&sAl[row0 * ST2 + col] = l2;
            splitb(c2, h2.x, l2.x); splitb(c3, h2.y, l2.y);
            *(__nv_bfloat162*)&sAh[row1 * ST2 + col] = h2;
            *(__nv_bfloat162*)&sAl[row1 * ST2 + col] = l2;
        }
    }
    __syncthreads();

    // ---------------- B-phase ----------------
    {
        const bool has_aux = (w & 1);
        float dO[5][4] = {};

        #pragma unroll
        for (int gsel = 0; gsel < 2; gsel++) {
            const __nv_bfloat16* Aoph = gsel ? sQh : sAh;
            const __nv_bfloat16* Aopl = gsel ? sQl : sAl;
            const __nv_bfloat16* Boph = gsel ? sSh : sVh;
            const __nv_bfloat16* Bopl = gsel ? sSl : sVl;
            #pragma unroll
            for (int ks = 0; ks < 4; ks++) {
                uint32_t ah[4], al[4];
                ldsm_x4(ah, smem_u32(&Aoph[(mrow + lhf*8 + lr) * ST2 + ks*16 + lnh*8]));
                ldsm_x4(al, smem_u32(&Aopl[(mrow + lhf*8 + lr) * ST2 + ks*16 + lnh*8]));
                uint32_t bh[4][2], bl[4][2];
                #pragma unroll
                for (int blk = 0; blk < 2; blk++) {
                    uint32_t r4[4];
                    ldsm_x4t(r4, smem_u32(&Boph[(ks*16 + lhf*8 + lr) * ST2 + jcol + blk*16 + lnh*8]));
                    bh[blk*2][0] = r4[0]; bh[blk*2][1] = r4[1];
                    bh[blk*2+1][0] = r4[2]; bh[blk*2+1][1] = r4[3];
                    ldsm_x4t(r4, smem_u32(&Bopl[(ks*16 + lhf*8 + lr) * ST2 + jcol + blk*16 + lnh*8]));
                    bl[blk*2][0] = r4[0]; bl[blk*2][1] = r4[1];
                    bl[blk*2+1][0] = r4[2]; bl[blk*2+1][1] = r4[3];
                }
                #pragma unroll
                for (int t = 0; t < 4; t++) {
                    mma_bf16(dO[t], ah, bh[t][0], bh[t][1]);
                    mma_bf16(dO[t], ah, bl[t][0], bl[t][1]);
                    mma_bf16(dO[t], al, bh[t][0], bh[t][1]);
                }
                if (has_aux) {
                    uint32_t bxh[2], bxl[2];
                    int r16 = lane & 15;
                    int rr  = (r16 & 7) + ((r16 >> 3) & 1) * 8;
                    ldsm_x2t(bxh, smem_u32(&Boph[(ks*16 + rr) * ST2 + 64]));
                    ldsm_x2t(bxl, smem_u32(&Bopl[(ks*16 + rr) * ST2 + 64]));
                    mma_bf16(dO[4], ah, bxh[0], bxh[1]);
                    mma_bf16(dO[4], ah, bxl[0], bxl[1]);
                    mma_bf16(dO[4], al, bxh[0], bxh[1]);
                }
            }
        }

        const int row0 = mrow + g;
        const int row1 = row0 + 8;

        if (has_aux && tig == 0) {
            sDen[row0] = 1.f / (dO[4][0] + EPSV);
            sDen[row1] = 1.f / (dO[4][2] + EPSV);
        }
        __syncthreads();

        const float inv0 = sDen[row0];
        const float inv1 = sDen[row1];
        #pragma unroll
        for (int t = 0; t < 4; t++) {
            int col = jcol + 8*t + 2*tig;
            *(float2*)&Og[base + (size_t)row0 * DDIM + col] =
                make_float2(dO[t][0] * inv0, dO[t][1] * inv0);
            *(float2*)&Og[base + (size_t)row1 * DDIM + col] =
                make_float2(dO[t][2] * inv1, dO[t][3] * inv1);
        }
    }
}

// ---------------------------------------------------------------------------
extern "C" void kernel_launch(void* const* d_in, const int* in_sizes, int n_in,
                              void* d_out, int out_size) {
    const float* Q = (const float*)d_in[0];
    const float* K = (const float*)d_in[1];
    const float* V = (const float*)d_in[2];
    float* O = (float*)d_out;

    const int SMEM1 = 4 * TILE_ELEMS * 2;                             // 36.9 KB
    const int SMEM3 = 10 * TILE_ELEMS * 2 + 64 * (int)sizeof(float);  // ~92.4 KB

    static int inited = 0;
    if (!inited) {
        cudaFuncSetAttribute(lin_phase1, cudaFuncAttributeMaxDynamicSharedMemorySize, SMEM1);
        cudaFuncSetAttribute(lin_phase3, cudaFuncAttributeMaxDynamicSharedMemorySize, SMEM3);
        inited = 1;
    }

    lin_phase1<<<NB, 256, SMEM1>>>(K, V);
    lin_phase2<<<HNUM * 8, 512>>>();
    lin_phase3<<<NB, 256, SMEM3>>>(Q, K, V, O);
}

// round 11
// speedup vs baseline: 1.6494x; 1.0569x over previous
#include <cuda_runtime.h>
#include <cuda_bf16.h>
#include <cstdint>

#define HNUM 16
#define NSEQ 2048
#define DDIM 64
#define CHK  64
#define NC   (NSEQ / CHK)      // 32 chunks
#define NB   (HNUM * NC)       // 512 (head, chunk) tiles
#define EPSV 1e-6f

// Scratch: per-(head,chunk) KV state (64x64) and K feature-sum (64).
__device__ float g_KV[(size_t)NB * DDIM * DDIM];   // 8 MB
__device__ float g_Kz[(size_t)NB * DDIM];          // 128 KB

__device__ __forceinline__ float fmap(float x) {
    return x > 0.f ? x + 1.f : __expf(x);
}

// ---- mma helpers ----
__device__ __forceinline__ uint32_t smem_u32(const void* p) {
    return (uint32_t)__cvta_generic_to_shared(p);
}
__device__ __forceinline__ void ldsm_x4(uint32_t a[4], uint32_t addr) {
    asm volatile("ldmatrix.sync.aligned.m8n8.x4.shared.b16 {%0,%1,%2,%3}, [%4];"
                 : "=r"(a[0]), "=r"(a[1]), "=r"(a[2]), "=r"(a[3]) : "r"(addr));
}
__device__ __forceinline__ void ldsm_x4t(uint32_t a[4], uint32_t addr) {
    asm volatile("ldmatrix.sync.aligned.m8n8.x4.trans.shared.b16 {%0,%1,%2,%3}, [%4];"
                 : "=r"(a[0]), "=r"(a[1]), "=r"(a[2]), "=r"(a[3]) : "r"(addr));
}
__device__ __forceinline__ void ldsm_x2t(uint32_t a[2], uint32_t addr) {
    asm volatile("ldmatrix.sync.aligned.m8n8.x2.trans.shared.b16 {%0,%1}, [%2];"
                 : "=r"(a[0]), "=r"(a[1]) : "r"(addr));
}
__device__ __forceinline__ void mma_bf16(float d[4], const uint32_t a[4],
                                         const uint32_t b0, const uint32_t b1) {
    asm volatile(
        "mma.sync.aligned.m16n8k16.row.col.f32.bf16.bf16.f32 "
        "{%0,%1,%2,%3}, {%4,%5,%6,%7}, {%8,%9}, {%0,%1,%2,%3};"
        : "+f"(d[0]), "+f"(d[1]), "+f"(d[2]), "+f"(d[3])
        : "r"(a[0]), "r"(a[1]), "r"(a[2]), "r"(a[3]), "r"(b0), "r"(b1));
}
__device__ __forceinline__ void splitb(float x, __nv_bfloat16& h, __nv_bfloat16& l) {
    h = __float2bfloat16(x);
    l = __float2bfloat16(x - __bfloat162float(h));
}

#define ST2 72
#define TILE_ELEMS (64 * ST2)

// ---------------------------------------------------------------------------
// Phase 1 (tensor-core): KV[d][e] = sum_m phiK[m][d] V[m][e]; aux col V[:,64]=1
// gives col 64 = Kz[d].  K stored ROW-MAJOR [m][d]; A-fragments via ldsm.trans
// (no transpose stores).  grid = NB (512), block = 256.
// ---------------------------------------------------------------------------
__global__ void __launch_bounds__(256) lin_phase1(const float* __restrict__ Kg,
                                                  const float* __restrict__ Vg) {
    extern __shared__ __nv_bfloat16 smb1[];
    __nv_bfloat16* sKh = smb1;                     // [m][d] row-major
    __nv_bfloat16* sKl = sKh + TILE_ELEMS;
    __nv_bfloat16* sVh = sKl + TILE_ELEMS;         // [m][e], col64 = 1
    __nv_bfloat16* sVl = sVh + TILE_ELEMS;

    const int tid = threadIdx.x;
    const size_t base = (size_t)blockIdx.x * (CHK * DDIM);

    // ---- load + fmap + split (all vectorized row-major stores) ----
    {
        const int m  = tid >> 2;          // 0..63
        const int c0 = (tid & 3) * 16;
        #pragma unroll
        for (int u = 0; u < 4; u++) {
            int col = c0 + 4 * u;
            float4 k = *(const float4*)(Kg + base + m * DDIM + col);
            float4 v = *(const float4*)(Vg + base + m * DDIM + col);
            float kv[4] = {fmap(k.x), fmap(k.y), fmap(k.z), fmap(k.w)};
            float vv[4] = {v.x, v.y, v.z, v.w};
            #pragma unroll
            for (int p = 0; p < 2; p++) {
                __nv_bfloat162 kh2, kl2, vh2, vl2;
                splitb(kv[2*p],   kh2.x, kl2.x);
                splitb(kv[2*p+1], kh2.y, kl2.y);
                splitb(vv[2*p],   vh2.x, vl2.x);
                splitb(vv[2*p+1], vh2.y, vl2.y);
                *(__nv_bfloat162*)&sKh[m * ST2 + col + 2*p] = kh2;
                *(__nv_bfloat162*)&sKl[m * ST2 + col + 2*p] = kl2;
                *(__nv_bfloat162*)&sVh[m * ST2 + col + 2*p] = vh2;
                *(__nv_bfloat162*)&sVl[m * ST2 + col + 2*p] = vl2;
            }
        }
        if (tid < 64) {                            // aux cols 64..71 of V
            sVh[tid * ST2 + 64] = __float2bfloat16(1.0f);
            sVl[tid * ST2 + 64] = __float2bfloat16(0.0f);
            #pragma unroll
            for (int c = 65; c < 72; c++) {
                sVh[tid * ST2 + c] = __float2bfloat16(0.0f);
                sVl[tid * ST2 + c] = __float2bfloat16(0.0f);
            }
        }
    }
    __syncthreads();

    const int w    = tid >> 5;
    const int lane = tid & 31;
    const int g    = lane >> 2;
    const int tig  = lane & 3;
    const int drow = (w >> 1) * 16;      // output row block (d)
    const int ecol = (w & 1) * 32;       // output col block (e)
    const int lr   = lane & 7;
    const int lhf  = (lane >> 3) & 1;
    const int lnh  = lane >> 4;
    const bool has_aux = (w & 1);

    float dO[5][4] = {};
    #pragma unroll
    for (int ks = 0; ks < 4; ks++) {     // k over m
        // A = phiK^T: trans-load from row-major K [m][d]
        uint32_t ah[4], al[4];
        ldsm_x4t(ah, smem_u32(&sKh[(ks*16 + lnh*8 + lr) * ST2 + drow + lhf*8]));
        ldsm_x4t(al, smem_u32(&sKl[(ks*16 + lnh*8 + lr) * ST2 + drow + lhf*8]));
        uint32_t bh[4][2], bl[4][2];
        #pragma unroll
        for (int blk = 0; blk < 2; blk++) {
            uint32_t r4[4];
            ldsm_x4t(r4, smem_u32(&sVh[(ks*16 + lhf*8 + lr) * ST2 + ecol + blk*16 + lnh*8]));
            bh[blk*2][0] = r4[0]; bh[blk*2][1] = r4[1];
            bh[blk*2+1][0] = r4[2]; bh[blk*2+1][1] = r4[3];
            ldsm_x4t(r4, smem_u32(&sVl[(ks*16 + lhf*8 + lr) * ST2 + ecol + blk*16 + lnh*8]));
            bl[blk*2][0] = r4[0]; bl[blk*2][1] = r4[1];
            bl[blk*2+1][0] = r4[2]; bl[blk*2+1][1] = r4[3];
        }
        #pragma unroll
        for (int t = 0; t < 4; t++) {
            mma_bf16(dO[t], ah, bh[t][0], bh[t][1]);
            mma_bf16(dO[t], ah, bl[t][0], bl[t][1]);
            mma_bf16(dO[t], al, bh[t][0], bh[t][1]);
        }
        if (has_aux) {
            uint32_t bxh[2], bxl[2];
            int r16 = lane & 15;
            int rr  = (r16 & 7) + ((r16 >> 3) & 1) * 8;
            ldsm_x2t(bxh, smem_u32(&sVh[(ks*16 + rr) * ST2 + 64]));
            ldsm_x2t(bxl, smem_u32(&sVl[(ks*16 + rr) * ST2 + 64]));
            mma_bf16(dO[4], ah, bxh[0], bxh[1]);
            mma_bf16(dO[4], ah, bxl[0], bxl[1]);
            mma_bf16(dO[4], al, bxh[0], bxh[1]);
        }
    }

    // write KV (fp32) and Kz
    float* kvo = g_KV + (size_t)blockIdx.x * (DDIM * DDIM);
    const int row0 = drow + g;
    const int row1 = row0 + 8;
    #pragma unroll
    for (int t = 0; t < 4; t++) {
        int col = ecol + 8*t + 2*tig;
        *(float2*)&kvo[row0 * DDIM + col] = make_float2(dO[t][0], dO[t][1]);
        *(float2*)&kvo[row1 * DDIM + col] = make_float2(dO[t][2], dO[t][3]);
    }
    if (has_aux && tig == 0) {
        g_Kz[(size_t)blockIdx.x * DDIM + row0] = dO[4][0];
        g_Kz[(size_t)blockIdx.x * DDIM + row1] = dO[4][2];
    }
}

// ---------------------------------------------------------------------------
// Phase 2: exclusive prefix over 32 chunks per head. [champion verbatim]
// ---------------------------------------------------------------------------
__global__ void __launch_bounds__(512) lin_phase2() {
    const int h = blockIdx.x >> 3;
    const int part = blockIdx.x & 7;
    const int idx = part * 512 + threadIdx.x;

    float run = 0.f;
    #pragma unroll
    for (int c = 0; c < NC; c++) {
        float* p = g_KV + ((size_t)(h * NC + c)) * (DDIM * DDIM) + idx;
        float v = *p;
        *p = run;
        run += v;
    }
    if (part == 0 && threadIdx.x < DDIM) {
        float rz = 0.f;
        #pragma unroll
        for (int c = 0; c < NC; c++) {
            float* p = g_Kz + (size_t)(h * NC + c) * DDIM + threadIdx.x;
            float v = *p;
            *p = rz;
            rz += v;
        }
    }
}

// ---------------------------------------------------------------------------
// Phase 3: tensor-core (bf16-split mma.sync).  K now stored ROW-MAJOR [j][d];
// A-phase B-fragments via non-trans ldsm from [n][k] storage (no transpose
// stores).  Everything else = R9/R10 champion.
// ---------------------------------------------------------------------------
__global__ void __launch_bounds__(256) lin_phase3(const float* __restrict__ Qg,
                                                  const float* __restrict__ Kg,
                                                  const float* __restrict__ Vg,
                                                  float* __restrict__ Og) {
    extern __shared__ __nv_bfloat16 smb[];
    __nv_bfloat16* sQh = smb;
    __nv_bfloat16* sQl = sQh + TILE_ELEMS;
    __nv_bfloat16* sKh = sQl + TILE_ELEMS;   // [j][d] row-major
    __nv_bfloat16* sKl = sKh + TILE_ELEMS;
    __nv_bfloat16* sVh = sKl + TILE_ELEMS;   // [k][e], col64 = 1
    __nv_bfloat16* sVl = sVh + TILE_ELEMS;
    __nv_bfloat16* sSh = sVl + TILE_ELEMS;   // [d][e], col64 = z
    __nv_bfloat16* sSl = sSh + TILE_ELEMS;
    __nv_bfloat16* sAh = sSl + TILE_ELEMS;   // [m][k] masked A
    __nv_bfloat16* sAl = sAh + TILE_ELEMS;
    float* sDen = (float*)(sAl + TILE_ELEMS);

    const int tid = threadIdx.x;
    const size_t base = (size_t)blockIdx.x * (CHK * DDIM);

    // ---------------- load + fmap + split (all row-major vectorized) ----------------
    {
        const int m  = tid >> 2;          // 0..63
        const int c0 = (tid & 3) * 16;
        #pragma unroll
        for (int u = 0; u < 4; u++) {
            int col = c0 + 4 * u;
            float4 q = *(const float4*)(Qg + base + m * DDIM + col);
            float4 k = *(const float4*)(Kg + base + m * DDIM + col);
            float4 v = *(const float4*)(Vg + base + m * DDIM + col);
            float qv[4] = {fmap(q.x), fmap(q.y), fmap(q.z), fmap(q.w)};
            float kv[4] = {fmap(k.x), fmap(k.y), fmap(k.z), fmap(k.w)};
            float vv[4] = {v.x, v.y, v.z, v.w};
            #pragma unroll
            for (int p = 0; p < 2; p++) {
                __nv_bfloat162 qh2, ql2, kh2, kl2, vh2, vl2;
                splitb(qv[2*p],   qh2.x, ql2.x);
                splitb(qv[2*p+1], qh2.y, ql2.y);
                splitb(kv[2*p],   kh2.x, kl2.x);
                splitb(kv[2*p+1], kh2.y, kl2.y);
                splitb(vv[2*p],   vh2.x, vl2.x);
                splitb(vv[2*p+1], vh2.y, vl2.y);
                *(__nv_bfloat162*)&sQh[m * ST2 + col + 2*p] = qh2;
                *(__nv_bfloat162*)&sQl[m * ST2 + col + 2*p] = ql2;
                *(__nv_bfloat162*)&sKh[m * ST2 + col + 2*p] = kh2;
                *(__nv_bfloat162*)&sKl[m * ST2 + col + 2*p] = kl2;
                *(__nv_bfloat162*)&sVh[m * ST2 + col + 2*p] = vh2;
                *(__nv_bfloat162*)&sVl[m * ST2 + col + 2*p] = vl2;
            }
        }
        const float4* Sg4 = (const float4*)(g_KV + (size_t)blockIdx.x * (DDIM * DDIM));
        #pragma unroll
        for (int s = 0; s < 4; s++) {
            int i4 = tid + s * 256;
            int d  = i4 >> 4;
            int e0 = (i4 & 15) * 4;
            float4 sv = Sg4[i4];
            float ss[4] = {sv.x, sv.y, sv.z, sv.w};
            #pragma unroll
            for (int p = 0; p < 2; p++) {
                __nv_bfloat162 h2, l2;
                splitb(ss[2*p],   h2.x, l2.x);
                splitb(ss[2*p+1], h2.y, l2.y);
                *(__nv_bfloat162*)&sSh[d * ST2 + e0 + 2*p] = h2;
                *(__nv_bfloat162*)&sSl[d * ST2 + e0 + 2*p] = l2;
            }
        }
        if (tid < 64) {
            float z = g_Kz[(size_t)blockIdx.x * DDIM + tid];
            __nv_bfloat16 zh, zl;
            splitb(z, zh, zl);
            sSh[tid * ST2 + 64] = zh;
            sSl[tid * ST2 + 64] = zl;
            sVh[tid * ST2 + 64] = __float2bfloat16(1.0f);
            sVl[tid * ST2 + 64] = __float2bfloat16(0.0f);
            #pragma unroll
            for (int c = 65; c < 72; c++) {
                sVh[tid * ST2 + c] = __float2bfloat16(0.0f);
                sVl[tid * ST2 + c] = __float2bfloat16(0.0f);
                sSh[tid * ST2 + c] = __float2bfloat16(0.0f);
                sSl[tid * ST2 + c] = __float2bfloat16(0.0f);
            }
        }
    }
    __syncthreads();

    const int w    = tid >> 5;
    const int lane = tid & 31;
    const int g    = lane >> 2;
    const int tig  = lane & 3;
    const int mrow = (w >> 1) * 16;
    const int jcol = (w & 1) * 32;
    const int lr  = lane & 7;
    const int lhf = (lane >> 3) & 1;
    const int lnh = lane >> 4;

    // ---------------- A-phase: A = phiQ phiK^T ----------------
    {
        float dA[4][4] = {};
        #pragma unroll
        for (int ks = 0; ks < 4; ks++) {
            uint32_t ah[4], al[4];
            ldsm_x4(ah, smem_u32(&sQh[(mrow + lhf*8 + lr) * ST2 + ks*16 + lnh*8]));
            ldsm_x4(al, smem_u32(&sQl[(mrow + lhf*8 + lr) * ST2 + ks*16 + lnh*8]));
            uint32_t bh[4][2], bl[4][2];
            #pragma unroll
            for (int blk = 0; blk < 2; blk++) {
                // non-trans ldsm from row-major K [j][d] gives B col fragments
                uint32_t r4[4];
                ldsm_x4(r4, smem_u32(&sKh[(jcol + blk*16 + lnh*8 + lr) * ST2 + ks*16 + lhf*8]));
                bh[blk*2][0] = r4[0]; bh[blk*2][1] = r4[1];
                bh[blk*2+1][0] = r4[2]; bh[blk*2+1][1] = r4[3];
                ldsm_x4(r4, smem_u32(&sKl[(jcol + blk*16 + lnh*8 + lr) * ST2 + ks*16 + lhf*8]));
                bl[blk*2][0] = r4[0]; bl[blk*2][1] = r4[1];
                bl[blk*2+1][0] = r4[2]; bl[blk*2+1][1] = r4[3];
            }
            #pragma unroll
            for (int t = 0; t < 4; t++) {
                mma_bf16(dA[t], ah, bh[t][0], bh[t][1]);
                mma_bf16(dA[t], ah, bl[t][0], bl[t][1]);
                mma_bf16(dA[t], al, bh[t][0], bh[t][1]);
            }
        }
        const int row0 = mrow + g;
        const int row1 = row0 + 8;
        #pragma unroll
        for (int t = 0; t < 4; t++) {
            int col = jcol + 8*t + 2*tig;
            float c0 = (col     <= row0) ? dA[t][0] : 0.f;
            float c1 = (col + 1 <= row0) ? dA[t][1] : 0.f;
            float c2 = (col     <= row1) ? dA[t][2] : 0.f;
            float c3 = (col + 1 <= row1) ? dA[t][3] : 0.f;
            __nv_bfloat162 h2, l2;
            splitb(c0, h2.x, l2.x); splitb(c1, h2.y, l2.y);
            *(__nv_bfloat162*)&sAh[row0 * ST2 + col] = h2;
            *(__nv_bfloat162*)&sAl[row0 * ST2 + col] = l2;
            splitb(c2, h2.x, l2.x); splitb(c3, h2.y, l2.y);
            *(__nv_bfloat162*)&sAh[row1 * ST2 + col] = h2;
            *(__nv_bfloat162*)&sAl[row1 * ST2 + col] = l2;
        }
    }
    __syncthreads();

    // ---------------- B-phase ----------------
    {
        const bool has_aux = (w & 1);
        float dO[5][4] = {};

        #pragma unroll
        for (int gsel = 0; gsel < 2; gsel++) {
            const __nv_bfloat16* Aoph = gsel ? sQh : sAh;
            const __nv_bfloat16* Aopl = gsel ? sQl : sAl;
            const __nv_bfloat16* Boph = gsel ? sSh : sVh;
            const __nv_bfloat16* Bopl = gsel ? sSl : sVl;
            #pragma unroll
            for (int ks = 0; ks < 4; ks++) {
                uint32_t ah[4], al[4];
                ldsm_x4(ah, smem_u32(&Aoph[(mrow + lhf*8 + lr) * ST2 + ks*16 + lnh*8]));
                ldsm_x4(al, smem_u32(&Aopl[(mrow + lhf*8 + lr) * ST2 + ks*16 + lnh*8]));
                uint32_t bh[4][2], bl[4][2];
                #pragma unroll
                for (int blk = 0; blk < 2; blk++) {
                    uint32_t r4[4];
                    ldsm_x4t(r4, smem_u32(&Boph[(ks*16 + lhf*8 + lr) * ST2 + jcol + blk*16 + lnh*8]));
                    bh[blk*2][0] = r4[0]; bh[blk*2][1] = r4[1];
                    bh[blk*2+1][0] = r4[2]; bh[blk*2+1][1] = r4[3];
                    ldsm_x4t(r4, smem_u32(&Bopl[(ks*16 + lhf*8 + lr) * ST2 + jcol + blk*16 + lnh*8]));
                    bl[blk*2][0] = r4[0]; bl[blk*2][1] = r4[1];
                    bl[blk*2+1][0] = r4[2]; bl[blk*2+1][1] = r4[3];
                }
                #pragma unroll
                for (int t = 0; t < 4; t++) {
                    mma_bf16(dO[t], ah, bh[t][0], bh[t][1]);
                    mma_bf16(dO[t], ah, bl[t][0], bl[t][1]);
                    mma_bf16(dO[t], al, bh[t][0], bh[t][1]);
                }
                if (has_aux) {
                    uint32_t bxh[2], bxl[2];
                    int r16 = lane & 15;
                    int rr  = (r16 & 7) + ((r16 >> 3) & 1) * 8;
                    ldsm_x2t(bxh, smem_u32(&Boph[(ks*16 + rr) * ST2 + 64]));
                    ldsm_x2t(bxl, smem_u32(&Bopl[(ks*16 + rr) * ST2 + 64]));
                    mma_bf16(dO[4], ah, bxh[0], bxh[1]);
                    mma_bf16(dO[4], ah, bxl[0], bxl[1]);
                    mma_bf16(dO[4], al, bxh[0], bxh[1]);
                }
            }
        }

        const int row0 = mrow + g;
        const int row1 = row0 + 8;

        if (has_aux && tig == 0) {
            sDen[row0] = 1.f / (dO[4][0] + EPSV);
            sDen[row1] = 1.f / (dO[4][2] + EPSV);
        }
        __syncthreads();

        const float inv0 = sDen[row0];
        const float inv1 = sDen[row1];
        #pragma unroll
        for (int t = 0; t < 4; t++) {
            int col = jcol + 8*t + 2*tig;
            *(float2*)&Og[base + (size_t)row0 * DDIM + col] =
                make_float2(dO[t][0] * inv0, dO[t][1] * inv0);
            *(float2*)&Og[base + (size_t)row1 * DDIM + col] =
                make_float2(dO[t][2] * inv1, dO[t][3] * inv1);
        }
    }
}

// ---------------------------------------------------------------------------
extern "C" void kernel_launch(void* const* d_in, const int* in_sizes, int n_in,
                              void* d_out, int out_size) {
    const float* Q = (const float*)d_in[0];
    const float* K = (const float*)d_in[1];
    const float* V = (const float*)d_in[2];
    float* O = (float*)d_out;

    const int SMEM1 = 4 * TILE_ELEMS * 2;                             // 36.9 KB
    const int SMEM3 = 10 * TILE_ELEMS * 2 + 64 * (int)sizeof(float);  // ~92.4 KB

    static int inited = 0;
    if (!inited) {
        cudaFuncSetAttribute(lin_phase1, cudaFuncAttributeMaxDynamicSharedMemorySize, SMEM1);
        cudaFuncSetAttribute(lin_phase3, cudaFuncAttributeMaxDynamicSharedMemorySize, SMEM3);
        inited = 1;
    }

    lin_phase1<<<NB, 256, SMEM1>>>(K, V);
    lin_phase2<<<HNUM * 8, 512>>>();
    lin_phase3<<<NB, 256, SMEM3>>>(Q, K, V, O);
}